// round 4
// baseline (speedup 1.0000x reference)
#include <cuda_runtime.h>
#include <cuda_bf16.h>

// 4096 possible 12-bit rows -> 32 floats each = 512 KB LUT in device global.
__device__ float g_lut[4096 * 32];
__device__ unsigned int g_done = 0;   // builder blocks completed
__device__ unsigned int g_exit = 0;   // blocks finished (for counter reset)

#define ROWS_PER_BLOCK 128
#define THREADS 256
#define NBUILD_BLOCKS 64

// Compute one (b, s) LUT entry (8 floats).
__device__ __forceinline__ void build_lut_item(int idx,
                                               const float* __restrict__ pat,
                                               const float* __restrict__ pos,
                                               const int*   __restrict__ conn)
{
    const int b = idx >> 2;
    const int s = idx & 3;

    const int bits3n = 3 * (s + 1);
    const int paddr  = b & ((1 << bits3n) - 1);   // last 3n columns, MSB-first

    float out[8];
    int pb = 0;
#pragma unroll
    for (int j = 0; j < 3; j++) {
        float v = __ldg(&pat[(s * 3 + j) * 4096 + paddr]);
        int bit = (v > 0.5f) ? 1 : 0;
        out[j]  = (float)bit;
        pb |= bit << j;
    }

    const int in_bits = bits3n + 3;
    const int nb      = (in_bits < 12) ? in_bits : 12;
#pragma unroll
    for (int k = 0; k < 5; k++) {
        int addr = 0;
        for (int j = 0; j < nb; j++) {
            int c   = __ldg(&conn[(s * 5 + k) * 12 + j]) % in_bits;
            int bit = (c < bits3n) ? ((paddr >> (bits3n - 1 - c)) & 1)
                                   : ((pb >> (c - bits3n)) & 1);
            addr |= bit << j;
        }
        out[3 + k] = __ldg(&pos[(s * 5 + k) * 4096 + addr]);
    }

    float4* dst = (float4*)&g_lut[b * 32 + s * 8];
    dst[0] = ((const float4*)out)[0];
    dst[1] = ((const float4*)out)[1];
}

// Fused kernel.
//   bid < 64 : build 256 LUT items first, then signal.
//   All blocks: stage 1+2 (input staging + pack) BEFORE the LUT gate, so build
//   latency overlaps the compulsory input stream. Then gated LUT gather + store.
__global__ __launch_bounds__(THREADS)
void fused_kernel(const int* __restrict__ tb,
                  float* __restrict__ out,
                  int nrows,
                  const float* __restrict__ pat,
                  const float* __restrict__ pos,
                  const int*   __restrict__ conn)
{
    __shared__ int s_bits[ROWS_PER_BLOCK * 12];   // 6144 B
    __shared__ int s_idx[ROWS_PER_BLOCK];

    const int tid = threadIdx.x;
    const int bid = blockIdx.x;

    // ---- Builder role ----
    if (bid < NBUILD_BLOCKS) {
        build_lut_item(bid * THREADS + tid, pat, pos, conn);
        __threadfence();          // publish LUT stores (gpu scope)
        __syncthreads();          // all 256 items of this block done
        if (tid == 0) atomicAdd(&g_done, 1u);
    }

    const int row_base = bid * ROWS_PER_BLOCK;
    const int rows     = min(ROWS_PER_BLOCK, nrows - row_base);

    if (rows > 0) {
        // Stage 1: coalesced int4 loads (rows*12 divisible by 4).
        const int n_int4 = (rows * 12) >> 2;
        const int4* src  = (const int4*)(tb + (size_t)row_base * 12);
        int4* dst        = (int4*)s_bits;
        for (int i = tid; i < n_int4; i += THREADS)
            dst[i] = __ldcs(src + i);
        __syncthreads();

        // Stage 2: pack 12 bits MSB-first per row.
        if (tid < rows) {
            const int* r = &s_bits[tid * 12];
            int b = 0;
#pragma unroll
            for (int c = 0; c < 12; c++)
                b |= r[c] << (11 - c);
            s_idx[tid] = b;
        }
        __syncthreads();

        // ---- LUT gate: wait until all 64 builder blocks have signalled ----
        if (tid == 0) {
            unsigned int v;
            do {
                asm volatile("ld.acquire.gpu.u32 %0, [%1];"
                             : "=r"(v) : "l"(&g_done) : "memory");
                if (v >= NBUILD_BLOCKS) break;
                __nanosleep(64);
            } while (true);
        }
        __syncthreads();
        __threadfence();   // gpu-scope acquire for all threads before LUT reads

        // Stage 3: 8 float4 chunks per row, coalesced.
        float4* out4 = (float4*)out + (size_t)row_base * 8;

        if (rows == ROWS_PER_BLOCK) {
            float4 v[4];
#pragma unroll
            for (int j = 0; j < 4; j++) {
                const int t     = tid + j * THREADS;
                const int row   = t >> 3;
                const int chunk = t & 7;
                v[j] = __ldg((const float4*)&g_lut[s_idx[row] * 32] + chunk);
            }
#pragma unroll
            for (int j = 0; j < 4; j++)
                __stcs(&out4[tid + j * THREADS], v[j]);
        } else {
            const int ntasks = rows * 8;
            for (int t = tid; t < ntasks; t += THREADS) {
                const int row   = t >> 3;
                const int chunk = t & 7;
                float4 v = __ldg((const float4*)&g_lut[s_idx[row] * 32] + chunk);
                __stcs(&out4[t], v);
            }
        }
    }

    // ---- Exit accounting: last block resets counters for the next replay ----
    __syncthreads();
    if (tid == 0) {
        unsigned int t = atomicAdd(&g_exit, 1u);
        if (t == gridDim.x - 1) {
            g_done = 0;
            g_exit = 0;
            __threadfence();
        }
    }
}

extern "C" void kernel_launch(void* const* d_in, const int* in_sizes, int n_in,
                              void* d_out, int out_size)
{
    const int*   tb   = (const int*)  d_in[0];  // type_bits      (B, 12) i32
    const float* pat  = (const float*)d_in[1];  // pattern_tables (4,3,4096) f32
    const float* pos  = (const float*)d_in[2];  // position_tables(4,5,4096) f32
    const int*   conn = (const int*)  d_in[3];  // position_conn  (4,5,12) i32
    float*       out  = (float*)d_out;          // (B, 4, 8) f32

    int nrows = in_sizes[0] / 12;

    int nblocks = (nrows + ROWS_PER_BLOCK - 1) / ROWS_PER_BLOCK;
    fused_kernel<<<nblocks, THREADS>>>(tb, out, nrows, pat, pos, conn);
}

// round 5
// speedup vs baseline: 1.0883x; 1.0883x over previous
#include <cuda_runtime.h>
#include <cuda_bf16.h>

// 4096 possible 12-bit rows -> 32 floats each = 512 KB LUT in device global.
__device__ float g_lut[4096 * 32];
__device__ unsigned int g_done = 0;   // builder blocks completed
__device__ unsigned int g_exit = 0;   // blocks finished (for counter reset)

#define ROWS_PER_BLOCK 128
#define THREADS 256
#define NBUILD_BLOCKS 64

// Compute one (b, s) LUT entry (8 floats).
__device__ __forceinline__ void build_lut_item(int idx,
                                               const float* __restrict__ pat,
                                               const float* __restrict__ pos,
                                               const int*   __restrict__ conn)
{
    const int b = idx >> 2;
    const int s = idx & 3;

    const int bits3n = 3 * (s + 1);
    const int paddr  = b & ((1 << bits3n) - 1);   // last 3n columns, MSB-first

    float out[8];
    int pb = 0;
#pragma unroll
    for (int j = 0; j < 3; j++) {
        float v = __ldg(&pat[(s * 3 + j) * 4096 + paddr]);
        int bit = (v > 0.5f) ? 1 : 0;
        out[j]  = (float)bit;
        pb |= bit << j;
    }

    const int in_bits = bits3n + 3;
    const int nb      = (in_bits < 12) ? in_bits : 12;
#pragma unroll
    for (int k = 0; k < 5; k++) {
        int addr = 0;
        for (int j = 0; j < nb; j++) {
            int c   = __ldg(&conn[(s * 5 + k) * 12 + j]) % in_bits;
            int bit = (c < bits3n) ? ((paddr >> (bits3n - 1 - c)) & 1)
                                   : ((pb >> (c - bits3n)) & 1);
            addr |= bit << j;
        }
        out[3 + k] = __ldg(&pos[(s * 5 + k) * 4096 + addr]);
    }

    float4* dst = (float4*)&g_lut[b * 32 + s * 8];
    dst[0] = ((const float4*)out)[0];
    dst[1] = ((const float4*)out)[1];
}

// Fused kernel.
//   bid < 64 : build 256 LUT items, then release-publish (one atomic per block).
//   All blocks: stage 1+2 (input staging + pack) BEFORE the LUT gate, so build
//   latency overlaps the compulsory input stream. Gate = tid0 acquire-spin +
//   bar.sync (two-phase acquire). NO gpu-scope fences in the consumer path —
//   __threadfence emits CCTL.IVALL on sm_103a and flushed L1 per block in R4.
__global__ __launch_bounds__(THREADS)
void fused_kernel(const int* __restrict__ tb,
                  float* __restrict__ out,
                  int nrows,
                  const float* __restrict__ pat,
                  const float* __restrict__ pos,
                  const int*   __restrict__ conn)
{
    __shared__ int s_bits[ROWS_PER_BLOCK * 12];   // 6144 B
    __shared__ int s_idx[ROWS_PER_BLOCK];

    const int tid = threadIdx.x;
    const int bid = blockIdx.x;

    // ---- Builder role ----
    if (bid < NBUILD_BLOCKS) {
        build_lut_item(bid * THREADS + tid, pat, pos, conn);
        __syncthreads();          // all 256 items of this block stored
        if (tid == 0) {
            // release-publish: orders this block's LUT stores before the add
            unsigned int one = 1u, ignored;
            asm volatile("atom.add.release.gpu.u32 %0, [%1], %2;"
                         : "=r"(ignored) : "l"(&g_done), "r"(one) : "memory");
        }
    }

    const int row_base = bid * ROWS_PER_BLOCK;
    const int rows     = min(ROWS_PER_BLOCK, nrows - row_base);

    if (rows > 0) {
        // Stage 1: coalesced int4 loads (rows*12 divisible by 4).
        const int n_int4 = (rows * 12) >> 2;
        const int4* src  = (const int4*)(tb + (size_t)row_base * 12);
        int4* dst        = (int4*)s_bits;
        for (int i = tid; i < n_int4; i += THREADS)
            dst[i] = __ldcs(src + i);
        __syncthreads();

        // Stage 2: pack 12 bits MSB-first per row.
        if (tid < rows) {
            const int* r = &s_bits[tid * 12];
            int b = 0;
#pragma unroll
            for (int c = 0; c < 12; c++)
                b |= r[c] << (11 - c);
            s_idx[tid] = b;
        }

        // ---- LUT gate: two-phase acquire (tid0 spin + bar.sync) ----
        if (tid == 0) {
            unsigned int v;
            do {
                asm volatile("ld.acquire.gpu.u32 %0, [%1];"
                             : "=r"(v) : "l"(&g_done) : "memory");
                if (v >= NBUILD_BLOCKS) break;
                __nanosleep(64);
            } while (true);
        }
        __syncthreads();   // covers stage-2 smem too

        // Stage 3: 8 float4 chunks per row, coalesced.
        float4* out4 = (float4*)out + (size_t)row_base * 8;

        if (rows == ROWS_PER_BLOCK) {
            float4 v[4];
#pragma unroll
            for (int j = 0; j < 4; j++) {
                const int t     = tid + j * THREADS;
                const int row   = t >> 3;
                const int chunk = t & 7;
                v[j] = __ldg((const float4*)&g_lut[s_idx[row] * 32] + chunk);
            }
#pragma unroll
            for (int j = 0; j < 4; j++)
                __stcs(&out4[tid + j * THREADS], v[j]);
        } else {
            const int ntasks = rows * 8;
            for (int t = tid; t < ntasks; t += THREADS) {
                const int row   = t >> 3;
                const int chunk = t & 7;
                float4 v = __ldg((const float4*)&g_lut[s_idx[row] * 32] + chunk);
                __stcs(&out4[t], v);
            }
        }
    }

    // ---- Exit accounting: last block resets counters for the next replay ----
    __syncthreads();
    if (tid == 0) {
        unsigned int t = atomicAdd(&g_exit, 1u);
        if (t == gridDim.x - 1) {
            g_done = 0;          // visible at kernel-completion boundary
            g_exit = 0;
        }
    }
}

extern "C" void kernel_launch(void* const* d_in, const int* in_sizes, int n_in,
                              void* d_out, int out_size)
{
    const int*   tb   = (const int*)  d_in[0];  // type_bits      (B, 12) i32
    const float* pat  = (const float*)d_in[1];  // pattern_tables (4,3,4096) f32
    const float* pos  = (const float*)d_in[2];  // position_tables(4,5,4096) f32
    const int*   conn = (const int*)  d_in[3];  // position_conn  (4,5,12) i32
    float*       out  = (float*)d_out;          // (B, 4, 8) f32

    int nrows = in_sizes[0] / 12;

    int nblocks = (nrows + ROWS_PER_BLOCK - 1) / ROWS_PER_BLOCK;
    fused_kernel<<<nblocks, THREADS>>>(tb, out, nrows, pat, pos, conn);
}

// round 6
// speedup vs baseline: 1.1692x; 1.0743x over previous
#include <cuda_runtime.h>
#include <cuda_bf16.h>

// 4096 possible 12-bit rows -> 32 floats each = 512 KB LUT in device global.
__device__ float g_lut[4096 * 32];
__device__ unsigned int g_done = 0;   // builder blocks completed
__device__ unsigned int g_exit = 0;   // blocks finished (for counter reset)

#define THREADS   256
#define RPB       128        // rows per tile
#define NBUILD    64         // builder blocks (first 64 bids -> wave-1 resident)
#define PBLOCKS   888        // persistent grid: 148 SMs x 6 blocks (reg-budget safe)

// Compute one (b, s) LUT entry (8 floats).
__device__ __forceinline__ void build_lut_item(int idx,
                                               const float* __restrict__ pat,
                                               const float* __restrict__ pos,
                                               const int*   __restrict__ conn)
{
    const int b = idx >> 2;
    const int s = idx & 3;

    const int bits3n = 3 * (s + 1);
    const int paddr  = b & ((1 << bits3n) - 1);   // last 3n columns, MSB-first

    float out[8];
    int pb = 0;
#pragma unroll
    for (int j = 0; j < 3; j++) {
        float v = __ldg(&pat[(s * 3 + j) * 4096 + paddr]);
        int bit = (v > 0.5f) ? 1 : 0;
        out[j]  = (float)bit;
        pb |= bit << j;
    }

    const int in_bits = bits3n + 3;
    const int nb      = (in_bits < 12) ? in_bits : 12;
#pragma unroll
    for (int k = 0; k < 5; k++) {
        int addr = 0;
        for (int j = 0; j < nb; j++) {
            int c   = __ldg(&conn[(s * 5 + k) * 12 + j]) % in_bits;
            int bit = (c < bits3n) ? ((paddr >> (bits3n - 1 - c)) & 1)
                                   : ((pb >> (c - bits3n)) & 1);
            addr |= bit << j;
        }
        out[3 + k] = __ldg(&pos[(s * 5 + k) * 4096 + addr]);
    }

    float4* dst = (float4*)&g_lut[b * 32 + s * 8];
    dst[0] = ((const float4*)out)[0];
    dst[1] = ((const float4*)out)[1];
}

// ---- tile stages (operate on smem staging buffers) ----

__device__ __forceinline__ void stage1_load(const int* __restrict__ tb,
                                            int* s_bits, int tile, int rows)
{
    const int n_int4 = (rows * 12) >> 2;              // rows*12 divisible by 4
    const int4* src  = (const int4*)(tb + (size_t)tile * RPB * 12);
    int4* dst        = (int4*)s_bits;
    for (int i = threadIdx.x; i < n_int4; i += THREADS)
        dst[i] = __ldcs(src + i);
}

__device__ __forceinline__ void stage2_pack(const int* s_bits, int* s_idx, int rows)
{
    const int tid = threadIdx.x;
    if (tid < rows) {
        const int* r = &s_bits[tid * 12];
        int b = 0;
#pragma unroll
        for (int c = 0; c < 12; c++)
            b |= r[c] << (11 - c);
        s_idx[tid] = b;
    }
}

__device__ __forceinline__ void stage3_gather(const int* s_idx,
                                              float* __restrict__ out,
                                              int tile, int rows)
{
    const int tid = threadIdx.x;
    float4* out4  = (float4*)out + (size_t)tile * RPB * 8;

    if (rows == RPB) {
        float4 v[4];
#pragma unroll
        for (int j = 0; j < 4; j++) {
            const int t     = tid + j * THREADS;
            const int row   = t >> 3;
            const int chunk = t & 7;
            v[j] = __ldg((const float4*)&g_lut[s_idx[row] * 32] + chunk);
        }
#pragma unroll
        for (int j = 0; j < 4; j++)
            __stcs(&out4[tid + j * THREADS], v[j]);
    } else {
        const int ntasks = rows * 8;
        for (int t = tid; t < ntasks; t += THREADS) {
            const int row   = t >> 3;
            const int chunk = t & 7;
            float4 v = __ldg((const float4*)&g_lut[s_idx[row] * 32] + chunk);
            __stcs(&out4[t], v);
        }
    }
}

// Persistent fused kernel: 888 blocks grid-stride over tiles.
// Builders (bid<64) compute 256 LUT items each, release-publish once.
// Every block: prefetch first tile BEFORE the gate (hides build latency),
// gate ONCE, then loop tiles with the plain 2-bar pipeline. No gpu fences.
__global__ __launch_bounds__(THREADS)
void fused_kernel(const int* __restrict__ tb,
                  float* __restrict__ out,
                  int nrows,
                  const float* __restrict__ pat,
                  const float* __restrict__ pos,
                  const int*   __restrict__ conn)
{
    __shared__ int s_bits[RPB * 12];   // 6144 B
    __shared__ int s_idx[RPB];

    const int tid = threadIdx.x;
    const int bid = blockIdx.x;

    // ---- Builder role (once) ----
    if (bid < NBUILD) {
        build_lut_item(bid * THREADS + tid, pat, pos, conn);
        __syncthreads();
        if (tid == 0) {
            unsigned int one = 1u, ignored;
            asm volatile("atom.add.release.gpu.u32 %0, [%1], %2;"
                         : "=r"(ignored) : "l"(&g_done), "r"(one) : "memory");
        }
    }

    const int ntiles = (nrows + RPB - 1) / RPB;
    int tile = bid;
    int rows = 0;

    // Prefetch first tile before gating.
    if (tile < ntiles) {
        rows = min(RPB, nrows - tile * RPB);
        stage1_load(tb, s_bits, tile, rows);
        __syncthreads();
        stage2_pack(s_bits, s_idx, rows);
    }

    // ---- LUT gate (ONCE per block): two-phase acquire ----
    if (tid == 0) {
        unsigned int v;
        do {
            asm volatile("ld.acquire.gpu.u32 %0, [%1];"
                         : "=r"(v) : "l"(&g_done) : "memory");
            if (v >= NBUILD) break;
            __nanosleep(64);
        } while (true);
    }
    __syncthreads();   // also orders stage2 smem for stage3

    // ---- Tile loop: 2 bars per tile, same as the fast split gather ----
    while (tile < ntiles) {
        stage3_gather(s_idx, out, tile, rows);

        tile += gridDim.x;
        if (tile >= ntiles) break;
        rows = min(RPB, nrows - tile * RPB);

        stage1_load(tb, s_bits, tile, rows);   // safe: prev stage2 done (bar above)
        __syncthreads();
        stage2_pack(s_bits, s_idx, rows);      // safe: all passed bar after stage3
        __syncthreads();
    }

    // ---- Exit accounting: last block resets counters for the next replay ----
    __syncthreads();
    if (tid == 0) {
        unsigned int t = atomicAdd(&g_exit, 1u);
        if (t == gridDim.x - 1) {
            g_done = 0;     // visible at kernel-completion boundary
            g_exit = 0;
        }
    }
}

extern "C" void kernel_launch(void* const* d_in, const int* in_sizes, int n_in,
                              void* d_out, int out_size)
{
    const int*   tb   = (const int*)  d_in[0];  // type_bits      (B, 12) i32
    const float* pat  = (const float*)d_in[1];  // pattern_tables (4,3,4096) f32
    const float* pos  = (const float*)d_in[2];  // position_tables(4,5,4096) f32
    const int*   conn = (const int*)  d_in[3];  // position_conn  (4,5,12) i32
    float*       out  = (float*)d_out;          // (B, 4, 8) f32

    int nrows = in_sizes[0] / 12;

    fused_kernel<<<PBLOCKS, THREADS>>>(tb, out, nrows, pat, pos, conn);
}

// round 7
// speedup vs baseline: 1.2117x; 1.0363x over previous
#include <cuda_runtime.h>
#include <cuda_bf16.h>

// 4096 possible 12-bit rows -> 32 floats each = 512 KB LUT in device global.
__device__ float g_lut[4096 * 32];
__device__ unsigned int g_done = 0;   // builder blocks completed
__device__ unsigned int g_exit = 0;   // blocks finished (for counter reset)

#define THREADS   256
#define RPB       128        // rows per tile
#define NBUILD    64         // builder blocks (bid<64 -> wave-1 resident)
#define PBLOCKS   1184       // 148 SMs x 8 blocks (32-reg budget)

// ---- LUT build: one (b, s) item per thread, conn staged in smem ----
__device__ __forceinline__ void build_lut_item(int idx,
                                               const float* __restrict__ pat,
                                               const float* __restrict__ pos,
                                               const int*   __restrict__ s_conn)
{
    const int b = idx >> 2;
    const int s = idx & 3;

    const int bits3n = 3 * (s + 1);
    const int paddr  = b & ((1 << bits3n) - 1);   // last 3n columns, MSB-first

    float out[8];
    int pb = 0;
#pragma unroll
    for (int j = 0; j < 3; j++) {
        float v = __ldg(&pat[(s * 3 + j) * 4096 + paddr]);
        int bit = (v > 0.5f) ? 1 : 0;
        out[j]  = (float)bit;
        pb |= bit << j;
    }

    const int in_bits = bits3n + 3;
    const int nb      = (in_bits < 12) ? in_bits : 12;
#pragma unroll
    for (int k = 0; k < 5; k++) {
        int addr = 0;
        for (int j = 0; j < nb; j++) {
            int c   = s_conn[(s * 5 + k) * 12 + j] % in_bits;
            int bit = (c < bits3n) ? ((paddr >> (bits3n - 1 - c)) & 1)
                                   : ((pb >> (c - bits3n)) & 1);
            addr |= bit << j;
        }
        out[3 + k] = __ldg(&pos[(s * 5 + k) * 4096 + addr]);
    }

    float4* dst = (float4*)&g_lut[b * 32 + s * 8];
    dst[0] = ((const float4*)out)[0];
    dst[1] = ((const float4*)out)[1];
}

// ---- tile stages ----

__device__ __forceinline__ void stage1_load(const int* __restrict__ tb,
                                            int* s_bits, int tile, int rows)
{
    const int n_int4 = (rows * 12) >> 2;              // rows*12 divisible by 4
    const int4* src  = (const int4*)(tb + (size_t)tile * RPB * 12);
    int4* dst        = (int4*)s_bits;
    for (int i = threadIdx.x; i < n_int4; i += THREADS)
        dst[i] = __ldcs(src + i);
}

__device__ __forceinline__ void stage2_pack(const int* s_bits, int* s_idx, int rows)
{
    const int tid = threadIdx.x;
    if (tid < rows) {
        const int* r = &s_bits[tid * 12];
        int b = 0;
#pragma unroll
        for (int c = 0; c < 12; c++)
            b |= r[c] << (11 - c);
        s_idx[tid] = b;
    }
}

__device__ __forceinline__ void stage3_gather(const int* s_idx,
                                              float* __restrict__ out,
                                              int tile, int rows)
{
    const int tid = threadIdx.x;
    float4* out4  = (float4*)out + (size_t)tile * RPB * 8;

    if (rows == RPB) {
        float4 v[4];
#pragma unroll
        for (int j = 0; j < 4; j++) {
            const int t     = tid + j * THREADS;
            const int row   = t >> 3;
            const int chunk = t & 7;
            v[j] = __ldg((const float4*)&g_lut[s_idx[row] * 32] + chunk);
        }
#pragma unroll
        for (int j = 0; j < 4; j++)
            __stcs(&out4[tid + j * THREADS], v[j]);
    } else {
        const int ntasks = rows * 8;
        for (int t = tid; t < ntasks; t += THREADS) {
            const int row   = t >> 3;
            const int chunk = t & 7;
            float4 v = __ldg((const float4*)&g_lut[s_idx[row] * 32] + chunk);
            __stcs(&out4[t], v);
        }
    }
}

// Persistent fused kernel, double-buffered:
//   iteration: issue next tile's input loads FIRST (independent, deep MLP),
//   then current tile's LUT gather + coalesced streaming store, bar, pack, bar.
__global__ __launch_bounds__(THREADS, 8)
void fused_kernel(const int* __restrict__ tb,
                  float* __restrict__ out,
                  int nrows,
                  const float* __restrict__ pat,
                  const float* __restrict__ pos,
                  const int*   __restrict__ conn)
{
    __shared__ int s_bits[2][RPB * 12];   // 2 x 6144 B
    __shared__ int s_idx[2][RPB];         // 2 x 512 B
    __shared__ int s_conn[60 * 4];        // 960 B (builders only)

    const int tid = threadIdx.x;
    const int bid = blockIdx.x;

    // ---- Builder role (once, before anything else) ----
    if (bid < NBUILD) {
        if (tid < 240) s_conn[tid] = __ldg(&conn[tid]);
        __syncthreads();
        build_lut_item(bid * THREADS + tid, pat, pos, s_conn);
        __syncthreads();
        if (tid == 0) {
            unsigned int one = 1u, ignored;
            asm volatile("atom.add.release.gpu.u32 %0, [%1], %2;"
                         : "=r"(ignored) : "l"(&g_done), "r"(one) : "memory");
        }
    }

    const int ntiles = (nrows + RPB - 1) / RPB;
    int tile = bid;
    int buf  = 0;
    int rows = 0;

    // Prefetch first tile before gating (overlaps build latency).
    if (tile < ntiles) {
        rows = min(RPB, nrows - tile * RPB);
        stage1_load(tb, s_bits[0], tile, rows);
        __syncthreads();
        stage2_pack(s_bits[0], s_idx[0], rows);
    }

    // ---- LUT gate (once per block): two-phase acquire, no gpu fence ----
    if (tid == 0) {
        unsigned int v;
        do {
            asm volatile("ld.acquire.gpu.u32 %0, [%1];"
                         : "=r"(v) : "l"(&g_done) : "memory");
            if (v >= NBUILD) break;
            __nanosleep(64);
        } while (true);
    }
    __syncthreads();   // also publishes stage-2 smem for stage3

    // ---- Double-buffered tile loop ----
    while (tile < ntiles) {
        const int next      = tile + gridDim.x;
        int       next_rows = 0;

        // 1) Issue next tile's input loads first (independent -> overlaps gather).
        if (next < ntiles) {
            next_rows = min(RPB, nrows - next * RPB);
            stage1_load(tb, s_bits[buf ^ 1], next, next_rows);
        }

        // 2) Current tile: LUT gather + coalesced streaming store.
        stage3_gather(s_idx[buf], out, tile, rows);

        __syncthreads();
        if (next < ntiles)
            stage2_pack(s_bits[buf ^ 1], s_idx[buf ^ 1], next_rows);
        __syncthreads();

        tile = next;
        rows = next_rows;
        buf ^= 1;
    }

    // ---- Exit accounting: last block resets counters for next graph replay ----
    if (tid == 0) {
        unsigned int t = atomicAdd(&g_exit, 1u);
        if (t == gridDim.x - 1) {
            g_done = 0;     // visible at kernel-completion boundary
            g_exit = 0;
        }
    }
}

extern "C" void kernel_launch(void* const* d_in, const int* in_sizes, int n_in,
                              void* d_out, int out_size)
{
    const int*   tb   = (const int*)  d_in[0];  // type_bits      (B, 12) i32
    const float* pat  = (const float*)d_in[1];  // pattern_tables (4,3,4096) f32
    const float* pos  = (const float*)d_in[2];  // position_tables(4,5,4096) f32
    const int*   conn = (const int*)  d_in[3];  // position_conn  (4,5,12) i32
    float*       out  = (float*)d_out;          // (B, 4, 8) f32

    int nrows = in_sizes[0] / 12;

    fused_kernel<<<PBLOCKS, THREADS>>>(tb, out, nrows, pat, pos, conn);
}